// round 11
// baseline (speedup 1.0000x reference)
#include <cuda_runtime.h>
#include <cuda_bf16.h>
#include <cstdint>
#include <cstddef>

#define N_AGT 100000
#define N_CTX 150000
#define NE    500000
#define D     128

#define TPB   512
#define ROWS  128   // rows per tile

// Wt slots in g_wt: 0=dist2 1=c1top 2=c2 3=q 4=c1mid 5=agt 6=lin 7=c1bot
__device__ float g_wt[8 * 128 * 128];
__device__ float g_qc[(size_t)N_AGT * D];
__device__ float g_cc[(size_t)N_CTX * D];
__device__ float g_abase[(size_t)N_AGT * D];

#define FMA2(d, a, b) asm("fma.rn.f32x2 %0, %1, %2, %0;" : "+l"(d) : "l"(a), "l"(b))

__device__ __forceinline__ void cp_async16(unsigned int s, const void* g) {
    asm volatile("cp.async.cg.shared.global [%0], [%1], 16;" :: "r"(s), "l"(g));
}
#define CP_COMMIT() asm volatile("cp.async.commit_group;" ::: "memory")
#define CP_WAIT(n)  asm volatile("cp.async.wait_group %0;" :: "n"(n) : "memory")

// ---------------------------------------------------------------------------
// Weight pre-transpose: g_wt[slot][j*128+k] = src[k*128+j]
// grid 512 x 256: blockIdx.x>>6 selects slot
// ---------------------------------------------------------------------------
__global__ void transpose_all(const float* __restrict__ W_dist2, const float* __restrict__ W_c1,
                              const float* __restrict__ W_c2,   const float* __restrict__ W_q,
                              const float* __restrict__ W_agt,  const float* __restrict__ W_lin) {
    int slot = blockIdx.x >> 6;
    int i = (blockIdx.x & 63) * 256 + threadIdx.x;   // 0..16383, i = k*128 + j
    const float* src;
    switch (slot) {
        case 0: src = W_dist2;        break;
        case 1: src = W_c1;           break;  // c1top (d part)
        case 2: src = W_c2;           break;
        case 3: src = W_q;            break;
        case 4: src = W_c1 + 16384;   break;  // c1mid (q part)
        case 5: src = W_agt;          break;
        case 6: src = W_lin;          break;
        default: src = W_c1 + 32768;  break;  // c1bot (ctx part)
    }
    int k = i >> 7, j = i & 127;
    g_wt[slot * 16384 + j * 128 + k] = src[i];
}

// ---------------------------------------------------------------------------
// Smem layouts (all float4, k-chunk-major):
//   Wbuf[kc*128 + j]   = (W[4kc][j], W[4kc+1][j], W[4kc+2][j], W[4kc+3][j])
//   Xbuf[kc*128 + row] = (X[row][4kc..4kc+3])
// Conflict-free LDS.128 in the gemm for both operands.
// ---------------------------------------------------------------------------

// prefetch a 128x128 weight matrix (stored transposed [j][k] in g_wt) into k-major smem
__device__ __forceinline__ void prefetch_w(float4* dst, const float* __restrict__ src, int tid) {
    unsigned int sb = (unsigned int)__cvta_generic_to_shared(dst);
#pragma unroll
    for (int i = 0; i < 8; i++) {
        int c = tid + i * TPB;              // chunk id 0..4095
        int j = c >> 5, kc = c & 31;        // coalesced over global rows
        cp_async16(sb + (unsigned int)((kc * 128 + j) * 16), src + j * 128 + kc * 4);
    }
}

// prefetch 128 data rows [row][k] row-major global into k-major smem
__device__ __forceinline__ void prefetch_rows(float4* dst, const float* __restrict__ src,
                                              int base, int nrows, int tid) {
    unsigned int sb = (unsigned int)__cvta_generic_to_shared(dst);
#pragma unroll
    for (int i = 0; i < 8; i++) {
        int c = tid + i * TPB;
        int r = c >> 5, kc = c & 31;
        int gr = base + r;
        if (gr > nrows - 1) gr = nrows - 1;
        cp_async16(sb + (unsigned int)((kc * 128 + r) * 16), src + (size_t)gr * D + kc * 4);
    }
}

// out[r][c] = sum_k X[row][k] * W[k][col],  row = ty*4+r, col = tx+16c
__device__ __forceinline__ void gemm_tile(const float4* __restrict__ Xs,
                                          const float4* __restrict__ Ws,
                                          int tx, int ty, float out[4][8]) {
    unsigned long long acc[4][8];
#pragma unroll
    for (int r = 0; r < 4; r++)
#pragma unroll
        for (int c = 0; c < 8; c++) acc[r][c] = 0ull;

    const float4* xb = Xs + ty * 4;
    const float4* wb = Ws + tx;

#pragma unroll 2
    for (int kc = 0; kc < 32; kc++) {
        ulonglong2 xv[4];
#pragma unroll
        for (int r = 0; r < 4; r++)
            xv[r] = *reinterpret_cast<const ulonglong2*>(xb + kc * 128 + r);
#pragma unroll
        for (int c = 0; c < 8; c++) {
            ulonglong2 wv = *reinterpret_cast<const ulonglong2*>(wb + kc * 128 + 16 * c);
#pragma unroll
            for (int r = 0; r < 4; r++) {
                FMA2(acc[r][c], xv[r].x, wv.x);
                FMA2(acc[r][c], xv[r].y, wv.y);
            }
        }
    }
#pragma unroll
    for (int r = 0; r < 4; r++)
#pragma unroll
        for (int c = 0; c < 8; c++) {
            float lo = __uint_as_float((unsigned)(acc[r][c] & 0xFFFFFFFFull));
            float hi = __uint_as_float((unsigned)(acc[r][c] >> 32));
            out[r][c] = lo + hi;
        }
}

__device__ __forceinline__ void gn_rows(float v[4][8], const float gg[8], const float bb[8],
                                        bool do_relu) {
#pragma unroll
    for (int r = 0; r < 4; r++) {
        float s = 0.f, q = 0.f;
#pragma unroll
        for (int c = 0; c < 8; c++) { s += v[r][c]; q += v[r][c] * v[r][c]; }
#pragma unroll
        for (int off = 1; off < 16; off <<= 1) {
            s += __shfl_xor_sync(0xFFFFFFFFu, s, off);
            q += __shfl_xor_sync(0xFFFFFFFFu, q, off);
        }
        float mu = s * (1.0f / 128.0f);
        float var = q * (1.0f / 128.0f) - mu * mu;
        float rstd = rsqrtf(fmaxf(var, 0.f) + 1e-5f);
#pragma unroll
        for (int c = 0; c < 8; c++) {
            float t = (v[r][c] - mu) * rstd * gg[c] + bb[c];
            v[r][c] = do_relu ? fmaxf(t, 0.f) : t;
        }
    }
}

// store tile (regs) into k-major float4 smem buffer (each thread owns its elements)
__device__ __forceinline__ void store_tile_f4(float* Xf, const float v[4][8], int tx, int ty) {
#pragma unroll
    for (int r = 0; r < 4; r++)
#pragma unroll
        for (int c = 0; c < 8; c++) {
            int col = tx + 16 * c, row = ty * 4 + r;
            Xf[((col >> 2) * 128 + row) * 4 + (col & 3)] = v[r][c];
        }
}

__device__ __forceinline__ void load_gb(const float* __restrict__ g, const float* __restrict__ b,
                                        int tx, float gg[8], float bb[8]) {
#pragma unroll
    for (int c = 0; c < 8; c++) { gg[c] = g[tx + 16 * c]; bb[c] = b[tx + 16 * c]; }
}

// ---------------------------------------------------------------------------
// Agent kernel: g_abase = agts@W_agt; q = relu(gn(agts@W_q)); g_qc = q@W_c1mid
// smem: W0, W1 (float4[4096] each), X (float4[4096])
// ---------------------------------------------------------------------------
__global__ __launch_bounds__(TPB, 1)
void agent_kernel(const float* __restrict__ agts,
                  const float* __restrict__ gq, const float* __restrict__ bq) {
    extern __shared__ float4 sm4[];
    float4* W0 = sm4;
    float4* W1 = sm4 + 4096;
    float4* X  = sm4 + 8192;
    int tid = threadIdx.x, tx = tid & 15, ty = tid >> 4;
    int base = blockIdx.x * ROWS;

    prefetch_rows(X, agts, base, N_AGT, tid); CP_COMMIT();   // G0
    prefetch_w(W0, g_wt + 5 * 16384, tid);    CP_COMMIT();   // G1: W_agt
    prefetch_w(W1, g_wt + 3 * 16384, tid);    CP_COMMIT();   // G2: W_q

    float v[4][8];
    CP_WAIT(1);             // X + W_agt ready
    __syncthreads();

    gemm_tile(X, W0, tx, ty, v);   // a = agts @ W_agt
#pragma unroll
    for (int r = 0; r < 4; r++) {
        int row = base + ty * 4 + r;
        if (row < N_AGT)
#pragma unroll
            for (int c = 0; c < 8; c++)
                g_abase[(size_t)row * D + tx + 16 * c] = v[r][c];
    }
    __syncthreads();                               // done reading W0
    prefetch_w(W0, g_wt + 4 * 16384, tid); CP_COMMIT();  // G3: W_c1mid
    CP_WAIT(1);             // W_q ready
    __syncthreads();

    gemm_tile(X, W1, tx, ty, v);   // agts @ W_q
    {
        float gg[8], bb[8];
        load_gb(gq, bq, tx, gg, bb);
        gn_rows(v, gg, bb, true);
    }
    __syncthreads();                               // everyone done reading X
    store_tile_f4((float*)X, v, tx, ty);
    CP_WAIT(0);
    __syncthreads();

    gemm_tile(X, W0, tx, ty, v);   // q @ W_c1mid
#pragma unroll
    for (int r = 0; r < 4; r++) {
        int row = base + ty * 4 + r;
        if (row < N_AGT)
#pragma unroll
            for (int c = 0; c < 8; c++)
                g_qc[(size_t)row * D + tx + 16 * c] = v[r][c];
    }
}

// ---------------------------------------------------------------------------
// Ctx kernel: g_cc = ctx @ W_c1bot
// smem: W0, X
// ---------------------------------------------------------------------------
__global__ __launch_bounds__(TPB, 1)
void ctx_kernel(const float* __restrict__ ctx) {
    extern __shared__ float4 sm4[];
    float4* W0 = sm4;
    float4* X  = sm4 + 4096;
    int tid = threadIdx.x, tx = tid & 15, ty = tid >> 4;
    int base = blockIdx.x * ROWS;

    prefetch_rows(X, ctx, base, N_CTX, tid); CP_COMMIT();
    prefetch_w(W0, g_wt + 7 * 16384, tid);    CP_COMMIT();
    CP_WAIT(0);
    __syncthreads();

    float v[4][8];
    gemm_tile(X, W0, tx, ty, v);
#pragma unroll
    for (int r = 0; r < 4; r++) {
        int row = base + ty * 4 + r;
        if (row < N_CTX)
#pragma unroll
            for (int c = 0; c < 8; c++)
                g_cc[(size_t)row * D + tx + 16 * c] = v[r][c];
    }
}

// ---------------------------------------------------------------------------
// Edge kernel: 128 edges per CTA, full pipeline, vector red scatter
// smem: W0, W1, X, hi/wi/dxy
// ---------------------------------------------------------------------------
__global__ __launch_bounds__(TPB, 1)
void edge_kernel(const float* __restrict__ agt_ctrs, const float* __restrict__ ctx_ctrs,
                 const float* __restrict__ W_dist1, const float* __restrict__ b_dist1,
                 const float* __restrict__ g_dist, const float* __restrict__ b_dist,
                 const float* __restrict__ g_c1, const float* __restrict__ b_c1,
                 const int* __restrict__ hi, const int* __restrict__ wi) {
    extern __shared__ float4 sm4[];
    float4* W0 = sm4;
    float4* W1 = sm4 + 4096;
    float4* X  = sm4 + 8192;
    int* s_hi    = (int*)(sm4 + 12288);
    int* s_wi    = s_hi + 128;
    float* s_dxy = (float*)(s_wi + 128);

    int tid = threadIdx.x, tx = tid & 15, ty = tid >> 4;
    int e0 = blockIdx.x * ROWS;

    prefetch_w(W0, g_wt + 0 * 16384, tid); CP_COMMIT();   // G0: W_dist2
    prefetch_w(W1, g_wt + 1 * 16384, tid); CP_COMMIT();   // G1: W_c1top

    if (tid < 128) {
        int e = e0 + tid;
        if (e > NE - 1) e = NE - 1;
        int h = hi[e], w = wi[e];
        s_hi[tid] = h;
        s_wi[tid] = w;
        s_dxy[2 * tid]     = agt_ctrs[2 * h]     - ctx_ctrs[2 * w];
        s_dxy[2 * tid + 1] = agt_ctrs[2 * h + 1] - ctx_ctrs[2 * w + 1];
    }
    __syncthreads();   // s_dxy visible

    // H1 = relu(d2 @ W_dist1 + b_dist1), straight into k-major X
#pragma unroll
    for (int i = 0; i < 8; i++) {
        int s = tid + i * TPB;      // f4 slot id
        int row = s & 127, kc = s >> 7;
        float dx = s_dxy[2 * row], dy = s_dxy[2 * row + 1];
        float4 w0 = *reinterpret_cast<const float4*>(&W_dist1[kc * 4]);
        float4 w1 = *reinterpret_cast<const float4*>(&W_dist1[128 + kc * 4]);
        float4 bb = *reinterpret_cast<const float4*>(&b_dist1[kc * 4]);
        float4 h;
        h.x = fmaxf(fmaf(dx, w0.x, fmaf(dy, w1.x, bb.x)), 0.f);
        h.y = fmaxf(fmaf(dx, w0.y, fmaf(dy, w1.y, bb.y)), 0.f);
        h.z = fmaxf(fmaf(dx, w0.z, fmaf(dy, w1.z, bb.z)), 0.f);
        h.w = fmaxf(fmaf(dx, w0.w, fmaf(dy, w1.w, bb.w)), 0.f);
        X[kc * 128 + row] = h;
    }
    CP_WAIT(1);          // W_dist2 ready
    __syncthreads();

    float v[4][8];
    // d = relu(gn(H1 @ W_dist2))
    gemm_tile(X, W0, tx, ty, v);
    {
        float gg[8], bb[8];
        load_gb(g_dist, b_dist, tx, gg, bb);
        gn_rows(v, gg, bb, true);
    }
    __syncthreads();                               // done reading X, W0
    store_tile_f4((float*)X, v, tx, ty);
    prefetch_w(W0, g_wt + 2 * 16384, tid); CP_COMMIT();   // G2: W_c2
    CP_WAIT(1);          // W_c1top ready
    __syncthreads();

    // c1 = relu(gn(d @ W_c1top + qc[hi] + cc[wi]))
    gemm_tile(X, W1, tx, ty, v);
#pragma unroll
    for (int r = 0; r < 4; r++) {
        int row = ty * 4 + r;
        size_t h = (size_t)s_hi[row];
        size_t w = (size_t)s_wi[row];
#pragma unroll
        for (int c = 0; c < 8; c++) {
            int col = tx + 16 * c;
            v[r][c] += g_qc[h * D + col] + g_cc[w * D + col];
        }
    }
    {
        float gg[8], bb[8];
        load_gb(g_c1, b_c1, tx, gg, bb);
        gn_rows(v, gg, bb, true);
    }
    __syncthreads();
    store_tile_f4((float*)X, v, tx, ty);
    CP_WAIT(0);          // W_c2 ready
    __syncthreads();

    // out = c1 @ W_c2 -> smem round-trip -> vector red scatter
    gemm_tile(X, W0, tx, ty, v);
    __syncthreads();                               // done reading X
    store_tile_f4((float*)X, v, tx, ty);
    __syncthreads();

#pragma unroll
    for (int i = 0; i < 8; i++) {
        int s = tid + i * TPB;
        int row = s & 127, kc = s >> 7;
        if (e0 + row < NE) {
            float4 val = X[kc * 128 + row];
            float* p = &g_abase[(size_t)s_hi[row] * D + kc * 4];
            asm volatile("red.global.add.v4.f32 [%0], {%1,%2,%3,%4};"
                         :: "l"(p), "f"(val.x), "f"(val.y), "f"(val.z), "f"(val.w)
                         : "memory");
        }
    }
}

// ---------------------------------------------------------------------------
// Final kernel: t = relu(gn(abase)); out = relu(gn(t@W_lin) + agts)
// smem: W0, X
// ---------------------------------------------------------------------------
__global__ __launch_bounds__(TPB, 1)
void final_kernel(const float* __restrict__ agts,
                  const float* __restrict__ gn_g, const float* __restrict__ gn_b,
                  const float* __restrict__ gl_g, const float* __restrict__ gl_b,
                  float* __restrict__ out) {
    extern __shared__ float4 sm4[];
    float4* W0 = sm4;
    float4* X  = sm4 + 4096;
    int tid = threadIdx.x, tx = tid & 15, ty = tid >> 4;
    int base = blockIdx.x * ROWS;

    prefetch_rows(X, g_abase, base, N_AGT, tid); CP_COMMIT();
    prefetch_w(W0, g_wt + 6 * 16384, tid);        CP_COMMIT();   // W_lin
    CP_WAIT(0);
    __syncthreads();

    float v[4][8];
    float* Xf = (float*)X;
    // each thread reads exactly the elements it will write back: no extra sync
#pragma unroll
    for (int r = 0; r < 4; r++)
#pragma unroll
        for (int c = 0; c < 8; c++) {
            int col = tx + 16 * c, row = ty * 4 + r;
            v[r][c] = Xf[((col >> 2) * 128 + row) * 4 + (col & 3)];
        }
    {
        float gg[8], bb[8];
        load_gb(gn_g, gn_b, tx, gg, bb);
        gn_rows(v, gg, bb, true);
    }
    store_tile_f4(Xf, v, tx, ty);
    __syncthreads();

    gemm_tile(X, W0, tx, ty, v);
    {
        float gg[8], bb[8];
        load_gb(gl_g, gl_b, tx, gg, bb);
        gn_rows(v, gg, bb, false);
    }
#pragma unroll
    for (int r = 0; r < 4; r++) {
        int row = base + ty * 4 + r;
        if (row < N_AGT) {
#pragma unroll
            for (int c = 0; c < 8; c++) {
                int col = tx + 16 * c;
                float t = v[r][c] + agts[(size_t)row * D + col];
                out[(size_t)row * D + col] = fmaxf(t, 0.f);
            }
        }
    }
}

// ---------------------------------------------------------------------------
// Launch
// ---------------------------------------------------------------------------
extern "C" void kernel_launch(void* const* d_in, const int* in_sizes, int n_in,
                              void* d_out, int out_size) {
    const float* agts     = (const float*)d_in[0];
    const float* ctx      = (const float*)d_in[1];
    const float* agt_ctrs = (const float*)d_in[2];
    const float* ctx_ctrs = (const float*)d_in[3];
    const float* W_dist1  = (const float*)d_in[4];
    const float* b_dist1  = (const float*)d_in[5];
    const float* W_dist2  = (const float*)d_in[6];
    const float* g_dist   = (const float*)d_in[7];
    const float* b_dist   = (const float*)d_in[8];
    const float* W_q      = (const float*)d_in[9];
    const float* g_q      = (const float*)d_in[10];
    const float* b_q      = (const float*)d_in[11];
    const float* W_c1     = (const float*)d_in[12];
    const float* g_c1     = (const float*)d_in[13];
    const float* b_c1     = (const float*)d_in[14];
    const float* W_c2     = (const float*)d_in[15];
    const float* W_agt    = (const float*)d_in[16];
    const float* g_n      = (const float*)d_in[17];
    const float* b_n      = (const float*)d_in[18];
    const float* W_lin    = (const float*)d_in[19];
    const float* g_lin    = (const float*)d_in[20];
    const float* b_lin    = (const float*)d_in[21];
    const int*   hi       = (const int*)d_in[22];
    const int*   wi       = (const int*)d_in[23];
    float* outp = (float*)d_out;

    const int BIG_SMEM = 12288 * 16 + 2048;   // W0 + W1 + X + edge misc = 198656
    const int SML_SMEM = 8192 * 16;           // W0 + X = 131072

    cudaFuncSetAttribute(agent_kernel, cudaFuncAttributeMaxDynamicSharedMemorySize, BIG_SMEM);
    cudaFuncSetAttribute(edge_kernel,  cudaFuncAttributeMaxDynamicSharedMemorySize, BIG_SMEM);
    cudaFuncSetAttribute(ctx_kernel,   cudaFuncAttributeMaxDynamicSharedMemorySize, SML_SMEM);
    cudaFuncSetAttribute(final_kernel, cudaFuncAttributeMaxDynamicSharedMemorySize, SML_SMEM);

    // 1) one-shot weight transposes (k contiguous per output column)
    transpose_all<<<512, 256>>>(W_dist2, W_c1, W_c2, W_q, W_agt, W_lin);

    // 2) per-node precomputes
    agent_kernel<<<(N_AGT + ROWS - 1) / ROWS, TPB, BIG_SMEM>>>(agts, g_q, b_q);
    ctx_kernel<<<(N_CTX + ROWS - 1) / ROWS, TPB, SML_SMEM>>>(ctx);

    // 3) per-edge pipeline + vector-red scatter
    edge_kernel<<<(NE + ROWS - 1) / ROWS, TPB, BIG_SMEM>>>(agt_ctrs, ctx_ctrs,
                                                           W_dist1, b_dist1,
                                                           g_dist, b_dist,
                                                           g_c1, b_c1,
                                                           hi, wi);

    // 4) final norm + linear + residual
    final_kernel<<<(N_AGT + ROWS - 1) / ROWS, TPB, SML_SMEM>>>(agts, g_n, b_n,
                                                               g_lin, b_lin, outp);
}

// round 14
// speedup vs baseline: 1.5740x; 1.5740x over previous
#include <cuda_runtime.h>
#include <cuda_bf16.h>
#include <cstdint>
#include <cstddef>

#define N_AGT 100000
#define N_CTX 150000
#define NE    500000
#define D     128

#define TPB   512
#define ROWS  128   // rows per tile (SIMT node kernels)
#define ETPB  256   // threads for mma edge kernel (8 warps)

// Wt slots in g_wt: 0=dist2 1=c1top 2=c2 3=q 4=c1mid 5=agt 6=lin 7=c1bot
// slots 0,1,2 tf32-rounded (edge mma path); 3..7 full fp32 (SIMT path)
__device__ float g_wt[8 * 128 * 128];
__device__ float g_qc[(size_t)N_AGT * D];
__device__ float g_cc[(size_t)N_CTX * D];
__device__ float g_abase[(size_t)N_AGT * D];

#define FMA2(d, a, b) asm("fma.rn.f32x2 %0, %1, %2, %0;" : "+l"(d) : "l"(a), "l"(b))

__device__ __forceinline__ void cp_async16(unsigned int s, const void* g) {
    asm volatile("cp.async.cg.shared.global [%0], [%1], 16;" :: "r"(s), "l"(g));
}
#define CP_COMMIT() asm volatile("cp.async.commit_group;" ::: "memory")
#define CP_WAIT(n)  asm volatile("cp.async.wait_group %0;" :: "n"(n) : "memory")

__device__ __forceinline__ float tf32r(float x) {
    unsigned int u;
    asm("cvt.rna.tf32.f32 %0, %1;" : "=r"(u) : "f"(x));
    return __uint_as_float(u);
}

// mma.sync m16n8k8 tf32: D = A@B + C (C==D), fp32 accum
__device__ __forceinline__ void mma8(float c[4],
                                     unsigned a0, unsigned a1, unsigned a2, unsigned a3,
                                     unsigned b0, unsigned b1) {
    asm volatile(
        "mma.sync.aligned.m16n8k8.row.col.f32.tf32.tf32.f32 "
        "{%0,%1,%2,%3}, {%4,%5,%6,%7}, {%8,%9}, {%0,%1,%2,%3};"
        : "+f"(c[0]), "+f"(c[1]), "+f"(c[2]), "+f"(c[3])
        : "r"(a0), "r"(a1), "r"(a2), "r"(a3), "r"(b0), "r"(b1));
}

// ---------------------------------------------------------------------------
// Weight pre-transpose: g_wt[slot][j*128+k] = src[k*128+j]; slots 0-2 tf32-rounded
// ---------------------------------------------------------------------------
__global__ void transpose_all(const float* __restrict__ W_dist2, const float* __restrict__ W_c1,
                              const float* __restrict__ W_c2,   const float* __restrict__ W_q,
                              const float* __restrict__ W_agt,  const float* __restrict__ W_lin) {
    int slot = blockIdx.x >> 6;
    int i = (blockIdx.x & 63) * 256 + threadIdx.x;   // i = k*128 + j
    const float* src;
    switch (slot) {
        case 0: src = W_dist2;        break;
        case 1: src = W_c1;           break;  // c1top (d part)
        case 2: src = W_c2;           break;
        case 3: src = W_q;            break;
        case 4: src = W_c1 + 16384;   break;  // c1mid (q part)
        case 5: src = W_agt;          break;
        case 6: src = W_lin;          break;
        default: src = W_c1 + 32768;  break;  // c1bot (ctx part)
    }
    int k = i >> 7, j = i & 127;
    float v = src[i];
    if (slot < 3) v = tf32r(v);
    g_wt[slot * 16384 + j * 128 + k] = v;
}

// ===========================================================================
// SIMT machinery (node kernels) — unchanged from R11 (passing)
// ===========================================================================
__device__ __forceinline__ void prefetch_w(float4* dst, const float* __restrict__ src, int tid) {
    unsigned int sb = (unsigned int)__cvta_generic_to_shared(dst);
#pragma unroll
    for (int i = 0; i < 8; i++) {
        int c = tid + i * TPB;
        int j = c >> 5, kc = c & 31;
        cp_async16(sb + (unsigned int)((kc * 128 + j) * 16), src + j * 128 + kc * 4);
    }
}

__device__ __forceinline__ void prefetch_rows(float4* dst, const float* __restrict__ src,
                                              int base, int nrows, int tid) {
    unsigned int sb = (unsigned int)__cvta_generic_to_shared(dst);
#pragma unroll
    for (int i = 0; i < 8; i++) {
        int c = tid + i * TPB;
        int r = c >> 5, kc = c & 31;
        int gr = base + r;
        if (gr > nrows - 1) gr = nrows - 1;
        cp_async16(sb + (unsigned int)((kc * 128 + r) * 16), src + (size_t)gr * D + kc * 4);
    }
}

__device__ __forceinline__ void gemm_tile(const float4* __restrict__ Xs,
                                          const float4* __restrict__ Ws,
                                          int tx, int ty, float out[4][8]) {
    unsigned long long acc[4][8];
#pragma unroll
    for (int r = 0; r < 4; r++)
#pragma unroll
        for (int c = 0; c < 8; c++) acc[r][c] = 0ull;

    const float4* xb = Xs + ty * 4;
    const float4* wb = Ws + tx;

#pragma unroll 2
    for (int kc = 0; kc < 32; kc++) {
        ulonglong2 xv[4];
#pragma unroll
        for (int r = 0; r < 4; r++)
            xv[r] = *reinterpret_cast<const ulonglong2*>(xb + kc * 128 + r);
#pragma unroll
        for (int c = 0; c < 8; c++) {
            ulonglong2 wv = *reinterpret_cast<const ulonglong2*>(wb + kc * 128 + 16 * c);
#pragma unroll
            for (int r = 0; r < 4; r++) {
                FMA2(acc[r][c], xv[r].x, wv.x);
                FMA2(acc[r][c], xv[r].y, wv.y);
            }
        }
    }
#pragma unroll
    for (int r = 0; r < 4; r++)
#pragma unroll
        for (int c = 0; c < 8; c++) {
            float lo = __uint_as_float((unsigned)(acc[r][c] & 0xFFFFFFFFull));
            float hi = __uint_as_float((unsigned)(acc[r][c] >> 32));
            out[r][c] = lo + hi;
        }
}

__device__ __forceinline__ void gn_rows(float v[4][8], const float gg[8], const float bb[8],
                                        bool do_relu) {
#pragma unroll
    for (int r = 0; r < 4; r++) {
        float s = 0.f, q = 0.f;
#pragma unroll
        for (int c = 0; c < 8; c++) { s += v[r][c]; q += v[r][c] * v[r][c]; }
#pragma unroll
        for (int off = 1; off < 16; off <<= 1) {
            s += __shfl_xor_sync(0xFFFFFFFFu, s, off);
            q += __shfl_xor_sync(0xFFFFFFFFu, q, off);
        }
        float mu = s * (1.0f / 128.0f);
        float var = q * (1.0f / 128.0f) - mu * mu;
        float rstd = rsqrtf(fmaxf(var, 0.f) + 1e-5f);
#pragma unroll
        for (int c = 0; c < 8; c++) {
            float t = (v[r][c] - mu) * rstd * gg[c] + bb[c];
            v[r][c] = do_relu ? fmaxf(t, 0.f) : t;
        }
    }
}

__device__ __forceinline__ void store_tile_f4(float* Xf, const float v[4][8], int tx, int ty) {
#pragma unroll
    for (int r = 0; r < 4; r++)
#pragma unroll
        for (int c = 0; c < 8; c++) {
            int col = tx + 16 * c, row = ty * 4 + r;
            Xf[((col >> 2) * 128 + row) * 4 + (col & 3)] = v[r][c];
        }
}

__device__ __forceinline__ void load_gb(const float* __restrict__ g, const float* __restrict__ b,
                                        int tx, float gg[8], float bb[8]) {
#pragma unroll
    for (int c = 0; c < 8; c++) { gg[c] = g[tx + 16 * c]; bb[c] = b[tx + 16 * c]; }
}

// ---------------------------------------------------------------------------
// Agent kernel (SIMT)
// ---------------------------------------------------------------------------
__global__ __launch_bounds__(TPB, 1)
void agent_kernel(const float* __restrict__ agts,
                  const float* __restrict__ gq, const float* __restrict__ bq) {
    extern __shared__ float4 sm4[];
    float4* W0 = sm4;
    float4* W1 = sm4 + 4096;
    float4* X  = sm4 + 8192;
    int tid = threadIdx.x, tx = tid & 15, ty = tid >> 4;
    int base = blockIdx.x * ROWS;

    prefetch_rows(X, agts, base, N_AGT, tid); CP_COMMIT();
    prefetch_w(W0, g_wt + 5 * 16384, tid);    CP_COMMIT();
    prefetch_w(W1, g_wt + 3 * 16384, tid);    CP_COMMIT();

    float v[4][8];
    CP_WAIT(1);
    __syncthreads();

    gemm_tile(X, W0, tx, ty, v);
#pragma unroll
    for (int r = 0; r < 4; r++) {
        int row = base + ty * 4 + r;
        if (row < N_AGT)
#pragma unroll
            for (int c = 0; c < 8; c++)
                g_abase[(size_t)row * D + tx + 16 * c] = v[r][c];
    }
    __syncthreads();
    prefetch_w(W0, g_wt + 4 * 16384, tid); CP_COMMIT();
    CP_WAIT(1);
    __syncthreads();

    gemm_tile(X, W1, tx, ty, v);
    {
        float gg[8], bb[8];
        load_gb(gq, bq, tx, gg, bb);
        gn_rows(v, gg, bb, true);
    }
    __syncthreads();
    store_tile_f4((float*)X, v, tx, ty);
    CP_WAIT(0);
    __syncthreads();

    gemm_tile(X, W0, tx, ty, v);
#pragma unroll
    for (int r = 0; r < 4; r++) {
        int row = base + ty * 4 + r;
        if (row < N_AGT)
#pragma unroll
            for (int c = 0; c < 8; c++)
                g_qc[(size_t)row * D + tx + 16 * c] = v[r][c];
    }
}

// ---------------------------------------------------------------------------
// Ctx kernel (SIMT)
// ---------------------------------------------------------------------------
__global__ __launch_bounds__(TPB, 1)
void ctx_kernel(const float* __restrict__ ctx) {
    extern __shared__ float4 sm4[];
    float4* W0 = sm4;
    float4* X  = sm4 + 4096;
    int tid = threadIdx.x, tx = tid & 15, ty = tid >> 4;
    int base = blockIdx.x * ROWS;

    prefetch_rows(X, ctx, base, N_CTX, tid); CP_COMMIT();
    prefetch_w(W0, g_wt + 7 * 16384, tid);    CP_COMMIT();
    CP_WAIT(0);
    __syncthreads();

    float v[4][8];
    gemm_tile(X, W0, tx, ty, v);
#pragma unroll
    for (int r = 0; r < 4; r++) {
        int row = base + ty * 4 + r;
        if (row < N_CTX)
#pragma unroll
            for (int c = 0; c < 8; c++)
                g_cc[(size_t)row * D + tx + 16 * c] = v[r][c];
    }
}

// ===========================================================================
// Edge kernel via mma.sync tf32. 256 threads, 128 edges/CTA.
// smem floats: Xs[128*132] | Wa[128*132] | Wb[128*132] | hi/wi/dxy
// Warp w owns output rows [16w, 16w+16): A-frag rows it reads, epi rows it
// writes — all X dependencies are warp-local; only W buffers need CTA syncs.
// ===========================================================================
#define XSTR 132

// stage 128x128 weight (row-major [n][k]) into smem [n*132+k]
__device__ __forceinline__ void stage_w132(float* dst, const float* __restrict__ src, int tid) {
    unsigned int sb = (unsigned int)__cvta_generic_to_shared(dst);
#pragma unroll
    for (int i = 0; i < 16; i++) {
        int c = tid + i * ETPB;          // 0..4095 float4 chunks
        int n = c >> 5, kg = c & 31;
        cp_async16(sb + (unsigned int)((n * XSTR + kg * 4) * 4), src + n * 128 + kg * 4);
    }
}

// warp GEMM: c[nt][0..3] += Xs[wr..wr+16) @ Ws^T  (Ws is [n][k], stride 132)
__device__ __forceinline__ void wgemm(const float* __restrict__ Xs,
                                      const float* __restrict__ Ws,
                                      int wr, int qr, int ql, float c[16][4]) {
#pragma unroll
    for (int nt = 0; nt < 16; nt++)
#pragma unroll
        for (int j = 0; j < 4; j++) c[nt][j] = 0.f;

    const float* xr = Xs + (wr + qr) * XSTR;   // a0/a2 row; a1/a3 at +8 rows
#pragma unroll
    for (int ks = 0; ks < 16; ks++) {
        int k0 = ks * 8;
        unsigned a0 = __float_as_uint(xr[k0 + ql]);
        unsigned a1 = __float_as_uint(xr[8 * XSTR + k0 + ql]);
        unsigned a2 = __float_as_uint(xr[k0 + 4 + ql]);
        unsigned a3 = __float_as_uint(xr[8 * XSTR + k0 + 4 + ql]);
#pragma unroll
        for (int nt = 0; nt < 16; nt++) {
            const float* wn = Ws + (nt * 8 + qr) * XSTR + k0 + ql;
            unsigned b0 = __float_as_uint(wn[0]);
            unsigned b1 = __float_as_uint(wn[4]);
            mma8(c[nt], a0, a1, a2, a3, b0, b1);
        }
    }
}

// GroupNorm(+relu) epilogue on mma fragments; optional +qc[hi]+cc[wi]; writes
// tf32-rounded result back into Xs (warp-local rows).
template <bool GATHER>
__device__ __forceinline__ void epi_gn_m(float c[16][4], float* __restrict__ Xs,
                                         const float* __restrict__ gv,
                                         const float* __restrict__ bv,
                                         const int* s_hi, const int* s_wi,
                                         int wr, int qr, int ql) {
    int r0 = wr + qr, r1 = r0 + 8;
    if (GATHER) {
        const float* q0 = g_qc + (size_t)s_hi[r0] * D;
        const float* c0 = g_cc + (size_t)s_wi[r0] * D;
        const float* q1 = g_qc + (size_t)s_hi[r1] * D;
        const float* c1 = g_cc + (size_t)s_wi[r1] * D;
#pragma unroll 4
        for (int nt = 0; nt < 16; nt++) {
            int col = nt * 8 + 2 * ql;
            float2 aq0 = *(const float2*)(q0 + col), ac0 = *(const float2*)(c0 + col);
            float2 aq1 = *(const float2*)(q1 + col), ac1 = *(const float2*)(c1 + col);
            c[nt][0] += aq0.x + ac0.x; c[nt][1] += aq0.y + ac0.y;
            c[nt][2] += aq1.x + ac1.x; c[nt][3] += aq1.y + ac1.y;
        }
    }
    float s0 = 0.f, s1 = 0.f, q0s = 0.f, q1s = 0.f;
#pragma unroll
    for (int nt = 0; nt < 16; nt++) {
        s0 += c[nt][0] + c[nt][1];
        s1 += c[nt][2] + c[nt][3];
        q0s += c[nt][0] * c[nt][0] + c[nt][1] * c[nt][1];
        q1s += c[nt][2] * c[nt][2] + c[nt][3] * c[nt][3];
    }
#pragma unroll
    for (int off = 1; off < 4; off <<= 1) {
        s0  += __shfl_xor_sync(0xFFFFFFFFu, s0, off);
        s1  += __shfl_xor_sync(0xFFFFFFFFu, s1, off);
        q0s += __shfl_xor_sync(0xFFFFFFFFu, q0s, off);
        q1s += __shfl_xor_sync(0xFFFFFFFFu, q1s, off);
    }
    float mu0 = s0 * (1.f / 128.f), mu1 = s1 * (1.f / 128.f);
    float rstd0 = rsqrtf(fmaxf(q0s * (1.f / 128.f) - mu0 * mu0, 0.f) + 1e-5f);
    float rstd1 = rsqrtf(fmaxf(q1s * (1.f / 128.f) - mu1 * mu1, 0.f) + 1e-5f);
#pragma unroll
    for (int nt = 0; nt < 16; nt++) {
        int col = nt * 8 + 2 * ql;
        float2 g2 = *(const float2*)(gv + col);
        float2 b2 = *(const float2*)(bv + col);
        float2 y0, y1;
        y0.x = tf32r(fmaxf((c[nt][0] - mu0) * rstd0 * g2.x + b2.x, 0.f));
        y0.y = tf32r(fmaxf((c[nt][1] - mu0) * rstd0 * g2.y + b2.y, 0.f));
        y1.x = tf32r(fmaxf((c[nt][2] - mu1) * rstd1 * g2.x + b2.x, 0.f));
        y1.y = tf32r(fmaxf((c[nt][3] - mu1) * rstd1 * g2.y + b2.y, 0.f));
        *(float2*)(Xs + r0 * XSTR + col) = y0;
        *(float2*)(Xs + r1 * XSTR + col) = y1;
    }
    __syncwarp();
}

__global__ __launch_bounds__(ETPB, 1)
void edge_kernel_m(const float* __restrict__ agt_ctrs, const float* __restrict__ ctx_ctrs,
                   const float* __restrict__ W_dist1, const float* __restrict__ b_dist1,
                   const float* __restrict__ g_dist, const float* __restrict__ b_dist,
                   const float* __restrict__ g_c1, const float* __restrict__ b_c1,
                   const int* __restrict__ hi, const int* __restrict__ wi) {
    extern __shared__ float sm[];
    float* Xs = sm;                     // 128*132
    float* Wa = sm + 128 * XSTR;        // 16896
    float* Wb = sm + 2 * 128 * XSTR;    // 33792
    int* s_hi    = (int*)(sm + 3 * 128 * XSTR);
    int* s_wi    = s_hi + 128;
    float* s_dxy = (float*)(s_wi + 128);

    int tid = threadIdx.x, lane = tid & 31, wid = tid >> 5;
    int wr = wid * 16;
    int qr = lane >> 2, ql = lane & 3;
    int e0 = blockIdx.x * 128;

    stage_w132(Wa, g_wt + 0 * 16384, tid); CP_COMMIT();   // G0: Wt_dist2
    stage_w132(Wb, g_wt + 1 * 16384, tid); CP_COMMIT();   // G1: Wt_c1top

    if (tid < 128) {
        int e = e0 + tid;
        if (e > NE - 1) e = NE - 1;
        int h = hi[e], w = wi[e];
        s_hi[tid] = h;
        s_wi[tid] = w;
        s_dxy[2 * tid]     = agt_ctrs[2 * h]     - ctx_ctrs[2 * w];
        s_dxy[2 * tid + 1] = agt_ctrs[2 * h + 1] - ctx_ctrs[2 * w + 1];
    }
    __syncthreads();

    // H1 = relu(dxy @ W_dist1 + b1) -> Xs (tf32), warp-local rows
    {
        int row = wr + (lane >> 1);
        int kg0 = (lane & 1) * 16;
        float dx = s_dxy[2 * row], dy = s_dxy[2 * row + 1];
#pragma unroll 4
        for (int i = 0; i < 16; i++) {
            int kg = kg0 + i;
            float4 w0 = *(const float4*)(W_dist1 + kg * 4);
            float4 w1 = *(const float4*)(W_dist1 + 128 + kg * 4);
            float4 bb = *(const float4*)(b_dist1 + kg * 4);
            float4 h;
            h.x = tf32r(fmaxf(fmaf(dx, w0.x, fmaf(dy, w1.x, bb.x)), 0.f));
            h.y = tf32r(fmaxf(fmaf(dx, w0.y, fmaf(dy, w1.y, bb.y)), 0.f));
            h.z = tf32r(fmaxf(fmaf(dx, w0.z, fmaf(dy, w1.z, bb.z)), 0.f));
            h.w = tf32r(fmaxf(fmaf(dx, w0.w, fmaf(dy, w1.w, bb.w)), 0.f));
            *(float4*)(Xs + row * XSTR + kg * 4) = h;
        }
    }
    CP_WAIT(1);          // Wa (dist2) landed
    __syncthreads();

    float c[16][4];

    // GEMM1: d_pre = H1 @ W_dist2;  epi1: d = relu(gn(d_pre)) -> Xs
    wgemm(Xs, Wa, wr, qr, ql, c);
    epi_gn_m<false>(c, Xs, g_dist, b_dist, nullptr, nullptr, wr, qr, ql);
    __syncthreads();                                      // all warps done with Wa
    stage_w132(Wa, g_wt + 2 * 16384, tid); CP_COMMIT();   // G2: Wt_c2
    CP_WAIT(1);          // Wb (c1top) landed
    __syncthreads();

    // GEMM2: c1_pre = d @ W_c1top;  epi2: c1 = relu(gn(c1_pre + qc[hi] + cc[wi])) -> Xs
    wgemm(Xs, Wb, wr, qr, ql, c);
    epi_gn_m<true>(c, Xs, g_c1, b_c1, s_hi, s_wi, wr, qr, ql);
    CP_WAIT(0);          // Wa (c2) landed
    __syncthreads();

    // GEMM3: out = c1 @ W_c2 -> vector red scatter into g_abase[hi]
    wgemm(Xs, Wa, wr, qr, ql, c);
    {
        int r0 = wr + qr, r1 = r0 + 8;
        bool ok0 = (e0 + r0) < NE, ok1 = (e0 + r1) < NE;
        float* a0p = g_abase + (size_t)s_hi[r0] * D;
        float* a1p = g_abase + (size_t)s_hi[r1] * D;
#pragma unroll
        for (int nt = 0; nt < 16; nt++) {
            int col = nt * 8 + 2 * ql;
            if (ok0)
                asm volatile("red.global.add.v2.f32 [%0], {%1,%2};"
                             :: "l"(a0p + col), "f"(c[nt][0]), "f"(c[nt][1]) : "memory");
            if (ok1)
                asm volatile("red.global.add.v2.f32 [%0], {%1,%2};"
                             :: "l"(a1p + col), "f"(c[nt][2]), "f"(c[nt][3]) : "memory");
        }
    }
}

// ---------------------------------------------------------------------------
// Final kernel (SIMT)
// ---------------------------------------------------------------------------
__global__ __launch_bounds__(TPB, 1)
void final_kernel(const float* __restrict__ agts,
                  const float* __restrict__ gn_g, const float* __restrict__ gn_b,
                  const float* __restrict__ gl_g, const float* __restrict__ gl_b,
                  float* __restrict__ out) {
    extern __shared__ float4 sm4[];
    float4* W0 = sm4;
    float4* X  = sm4 + 4096;
    int tid = threadIdx.x, tx = tid & 15, ty = tid >> 4;
    int base = blockIdx.x * ROWS;

    prefetch_rows(X, g_abase, base, N_AGT, tid); CP_COMMIT();
    prefetch_w(W0, g_wt + 6 * 16384, tid);        CP_COMMIT();
    CP_WAIT(0);
    __syncthreads();

    float v[4][8];
    float* Xf = (float*)X;
#pragma unroll
    for (int r = 0; r < 4; r++)
#pragma unroll
        for (int c = 0; c < 8; c++) {
            int col = tx + 16 * c, row = ty * 4 + r;
            v[r][c] = Xf[((col >> 2) * 128 + row) * 4 + (col & 3)];
        }
    {
        float gg[8], bb[8];
        load_gb(gn_g, gn_b, tx, gg, bb);
        gn_rows(v, gg, bb, true);
    }
    store_tile_f4(Xf, v, tx, ty);
    __syncthreads();

    gemm_tile(X, W0, tx, ty, v);
    {
        float gg[8], bb[8];
        load_gb(gl_g, gl_b, tx, gg, bb);
        gn_rows(v, gg, bb, false);
    }
#pragma unroll
    for (int r = 0; r < 4; r++) {
        int row = base + ty * 4 + r;
        if (row < N_AGT) {
#pragma unroll
            for (int c = 0; c < 8; c++) {
                int col = tx + 16 * c;
                float t = v[r][c] + agts[(size_t)row * D + col];
                out[(size_t)row * D + col] = fmaxf(t, 0.f);
            }
        }
    }
}

// ---------------------------------------------------------------------------
// Launch
// ---------------------------------------------------------------------------
extern "C" void kernel_launch(void* const* d_in, const int* in_sizes, int n_in,
                              void* d_out, int out_size) {
    const float* agts     = (const float*)d_in[0];
    const float* ctx      = (const float*)d_in[1];
    const float* agt_ctrs = (const float*)d_in[2];
    const float* ctx_ctrs = (const float*)d_in[3];
    const float* W_dist1  = (const float*)d_in[4];
    const float* b_dist1  = (const float*)d_in[5];
    const float* W_dist2  = (const float*)d_in[6];
    const float* g_dist   = (const float*)d_in[7];
    const float* b_dist   = (const float*)d_in[8];
    const float* W_q      = (const float*)d_in[9];
    const float* g_q      = (const float*)d_in[10];
    const float* b_q      = (const float*)d_in[11];
    const float* W_c1     = (const float*)d_in[12];
    const float* g_c1     = (const float*)d_in[13];
    const float* b_c1     = (const float*)d_in[14];
    const float* W_c2     = (const float*)d_in[15];
    const float* W_agt    = (const float*)d_in[16];
    const float* g_n      = (const float*)d_in[17];
    const float* b_n      = (const float*)d_in[18];
    const float* W_lin    = (const float*)d_in[19];
    const float* g_lin    = (const float*)d_in[20];
    const float* b_lin    = (const float*)d_in[21];
    const int*   hi       = (const int*)d_in[22];
    const int*   wi       = (const int*)d_in[23];
    float* outp = (float*)d_out;

    const int AGENT_SMEM = 12288 * 16;                       // 196608
    const int SML_SMEM   = 8192 * 16;                        // 131072
    const int EDGE_SMEM  = (3 * 128 * XSTR + 512) * 4;       // 204800

    cudaFuncSetAttribute(agent_kernel,  cudaFuncAttributeMaxDynamicSharedMemorySize, AGENT_SMEM);
    cudaFuncSetAttribute(ctx_kernel,    cudaFuncAttributeMaxDynamicSharedMemorySize, SML_SMEM);
    cudaFuncSetAttribute(edge_kernel_m, cudaFuncAttributeMaxDynamicSharedMemorySize, EDGE_SMEM);
    cudaFuncSetAttribute(final_kernel,  cudaFuncAttributeMaxDynamicSharedMemorySize, SML_SMEM);

    // 1) weight transposes (slots 0-2 tf32-rounded for the mma path)
    transpose_all<<<512, 256>>>(W_dist2, W_c1, W_c2, W_q, W_agt, W_lin);

    // 2) per-node precomputes (SIMT)
    agent_kernel<<<(N_AGT + ROWS - 1) / ROWS, TPB, AGENT_SMEM>>>(agts, g_q, b_q);
    ctx_kernel<<<(N_CTX + ROWS - 1) / ROWS, TPB, SML_SMEM>>>(ctx);

    // 3) per-edge pipeline on tensor cores (mma.sync tf32) + vector red scatter
    edge_kernel_m<<<(NE + 127) / 128, ETPB, EDGE_SMEM>>>(agt_ctrs, ctx_ctrs,
                                                         W_dist1, b_dist1,
                                                         g_dist, b_dist,
                                                         g_c1, b_c1,
                                                         hi, wi);

    // 4) final norm + linear + residual (SIMT)
    final_kernel<<<(N_AGT + ROWS - 1) / ROWS, TPB, SML_SMEM>>>(agts, g_n, b_n,
                                                               g_lin, b_lin, outp);
}

// round 16
// speedup vs baseline: 1.6102x; 1.0230x over previous
#include <cuda_runtime.h>
#include <cuda_bf16.h>
#include <cstdint>
#include <cstddef>

#define N_AGT 100000
#define N_CTX 150000
#define NE    500000
#define D     128

#define TPB   512
#define ROWS  128   // rows per tile (SIMT node kernels)
#define ETPB  256   // threads for mma edge kernel (8 warps)
#define XSTR  132

// Wt slots in g_wt: 0=dist2 1=c1top 2=c2 3=q 4=c1mid 5=agt 6=lin 7=c1bot
__device__ float g_wt[8 * 128 * 128];
// fragment-packed tf32 B operands for edge path: 0=dist2 1=c1top 2=c2
__device__ float g_wp[3 * 128 * 128];
__device__ float g_qc[(size_t)N_AGT * D];
__device__ float g_cc[(size_t)N_CTX * D];
__device__ float g_abase[(size_t)N_AGT * D];

#define FMA2(d, a, b) asm("fma.rn.f32x2 %0, %1, %2, %0;" : "+l"(d) : "l"(a), "l"(b))

__device__ __forceinline__ void cp_async16(unsigned int s, const void* g) {
    asm volatile("cp.async.cg.shared.global [%0], [%1], 16;" :: "r"(s), "l"(g));
}
#define CP_COMMIT() asm volatile("cp.async.commit_group;" ::: "memory")
#define CP_WAIT(n)  asm volatile("cp.async.wait_group %0;" :: "n"(n) : "memory")

__device__ __forceinline__ float tf32r(float x) {
    unsigned int u;
    asm("cvt.rna.tf32.f32 %0, %1;" : "=r"(u) : "f"(x));
    return __uint_as_float(u);
}

// mma.sync m16n8k8 tf32: D = A@B + C (C==D), fp32 accum
__device__ __forceinline__ void mma8(float c[4],
                                     unsigned a0, unsigned a1, unsigned a2, unsigned a3,
                                     unsigned b0, unsigned b1) {
    asm volatile(
        "mma.sync.aligned.m16n8k8.row.col.f32.tf32.tf32.f32 "
        "{%0,%1,%2,%3}, {%4,%5,%6,%7}, {%8,%9}, {%0,%1,%2,%3};"
        : "+f"(c[0]), "+f"(c[1]), "+f"(c[2]), "+f"(c[3])
        : "r"(a0), "r"(a1), "r"(a2), "r"(a3), "r"(b0), "r"(b1));
}

// ---------------------------------------------------------------------------
// Weight pre-transpose for SIMT node path: g_wt[slot][j*128+k] = src[k*128+j]
// ---------------------------------------------------------------------------
__global__ void transpose_all(const float* __restrict__ W_q, const float* __restrict__ W_c1,
                              const float* __restrict__ W_agt, const float* __restrict__ W_lin) {
    int slot = blockIdx.x >> 6;                      // 0..4
    int i = (blockIdx.x & 63) * 256 + threadIdx.x;   // i = k*128 + j
    const float* src;
    int dslot;
    switch (slot) {
        case 0: src = W_q;            dslot = 3; break;
        case 1: src = W_c1 + 16384;   dslot = 4; break;  // c1mid (q part)
        case 2: src = W_agt;          dslot = 5; break;
        case 3: src = W_lin;          dslot = 6; break;
        default: src = W_c1 + 32768;  dslot = 7; break;  // c1bot (ctx part)
    }
    int k = i >> 7, j = i & 127;
    g_wt[dslot * 16384 + j * 128 + k] = src[i];
}

// ---------------------------------------------------------------------------
// Fragment-pack B operands (tf32) for the edge mma path.
// Layout: float2 index p = ((ks*2+ch)*8+nt)*32+lane; comp in {0,1}.
//   n = ch*64 + nt*8 + (lane>>2),  k = ks*8 + (lane&3) + comp*4
//   value = tf32(W_src[k][n])       (W_src row-major [k][n])
// ---------------------------------------------------------------------------
__global__ void pack_b(const float* __restrict__ W_dist2, const float* __restrict__ W_c1,
                       const float* __restrict__ W_c2) {
    int i = blockIdx.x * 256 + threadIdx.x;          // 0..49151
    int slot = i >> 14, f = i & 16383;
    const float* src = (slot == 0) ? W_dist2 : ((slot == 1) ? W_c1 : W_c2);
    int comp = f & 1, p = f >> 1;
    int lane = p & 31;
    int t = p >> 5;
    int nt = t & 7;  t >>= 3;
    int ch = t & 1;  int ks = t >> 1;
    int qr = lane >> 2, ql = lane & 3;
    int n = ch * 64 + nt * 8 + qr;
    int k = ks * 8 + ql + comp * 4;
    g_wp[slot * 16384 + f] = tf32r(src[k * 128 + n]);
}

// ===========================================================================
// SIMT machinery (node kernels) — unchanged from R11/R14 (passing)
// ===========================================================================
__device__ __forceinline__ void prefetch_w(float4* dst, const float* __restrict__ src, int tid) {
    unsigned int sb = (unsigned int)__cvta_generic_to_shared(dst);
#pragma unroll
    for (int i = 0; i < 8; i++) {
        int c = tid + i * TPB;
        int j = c >> 5, kc = c & 31;
        cp_async16(sb + (unsigned int)((kc * 128 + j) * 16), src + j * 128 + kc * 4);
    }
}

__device__ __forceinline__ void prefetch_rows(float4* dst, const float* __restrict__ src,
                                              int base, int nrows, int tid) {
    unsigned int sb = (unsigned int)__cvta_generic_to_shared(dst);
#pragma unroll
    for (int i = 0; i < 8; i++) {
        int c = tid + i * TPB;
        int r = c >> 5, kc = c & 31;
        int gr = base + r;
        if (gr > nrows - 1) gr = nrows - 1;
        cp_async16(sb + (unsigned int)((kc * 128 + r) * 16), src + (size_t)gr * D + kc * 4);
    }
}

__device__ __forceinline__ void gemm_tile(const float4* __restrict__ Xs,
                                          const float4* __restrict__ Ws,
                                          int tx, int ty, float out[4][8]) {
    unsigned long long acc[4][8];
#pragma unroll
    for (int r = 0; r < 4; r++)
#pragma unroll
        for (int c = 0; c < 8; c++) acc[r][c] = 0ull;

    const float4* xb = Xs + ty * 4;
    const float4* wb = Ws + tx;

#pragma unroll 2
    for (int kc = 0; kc < 32; kc++) {
        ulonglong2 xv[4];
#pragma unroll
        for (int r = 0; r < 4; r++)
            xv[r] = *reinterpret_cast<const ulonglong2*>(xb + kc * 128 + r);
#pragma unroll
        for (int c = 0; c < 8; c++) {
            ulonglong2 wv = *reinterpret_cast<const ulonglong2*>(wb + kc * 128 + 16 * c);
#pragma unroll
            for (int r = 0; r < 4; r++) {
                FMA2(acc[r][c], xv[r].x, wv.x);
                FMA2(acc[r][c], xv[r].y, wv.y);
            }
        }
    }
#pragma unroll
    for (int r = 0; r < 4; r++)
#pragma unroll
        for (int c = 0; c < 8; c++) {
            float lo = __uint_as_float((unsigned)(acc[r][c] & 0xFFFFFFFFull));
            float hi = __uint_as_float((unsigned)(acc[r][c] >> 32));
            out[r][c] = lo + hi;
        }
}

__device__ __forceinline__ void gn_rows(float v[4][8], const float gg[8], const float bb[8],
                                        bool do_relu) {
#pragma unroll
    for (int r = 0; r < 4; r++) {
        float s = 0.f, q = 0.f;
#pragma unroll
        for (int c = 0; c < 8; c++) { s += v[r][c]; q += v[r][c] * v[r][c]; }
#pragma unroll
        for (int off = 1; off < 16; off <<= 1) {
            s += __shfl_xor_sync(0xFFFFFFFFu, s, off);
            q += __shfl_xor_sync(0xFFFFFFFFu, q, off);
        }
        float mu = s * (1.0f / 128.0f);
        float var = q * (1.0f / 128.0f) - mu * mu;
        float rstd = rsqrtf(fmaxf(var, 0.f) + 1e-5f);
#pragma unroll
        for (int c = 0; c < 8; c++) {
            float t = (v[r][c] - mu) * rstd * gg[c] + bb[c];
            v[r][c] = do_relu ? fmaxf(t, 0.f) : t;
        }
    }
}

__device__ __forceinline__ void store_tile_f4(float* Xf, const float v[4][8], int tx, int ty) {
#pragma unroll
    for (int r = 0; r < 4; r++)
#pragma unroll
        for (int c = 0; c < 8; c++) {
            int col = tx + 16 * c, row = ty * 4 + r;
            Xf[((col >> 2) * 128 + row) * 4 + (col & 3)] = v[r][c];
        }
}

__device__ __forceinline__ void load_gb(const float* __restrict__ g, const float* __restrict__ b,
                                        int tx, float gg[8], float bb[8]) {
#pragma unroll
    for (int c = 0; c < 8; c++) { gg[c] = g[tx + 16 * c]; bb[c] = b[tx + 16 * c]; }
}

// ---------------------------------------------------------------------------
// Agent kernel (SIMT)
// ---------------------------------------------------------------------------
__global__ __launch_bounds__(TPB, 1)
void agent_kernel(const float* __restrict__ agts,
                  const float* __restrict__ gq, const float* __restrict__ bq) {
    extern __shared__ float4 sm4[];
    float4* W0 = sm4;
    float4* W1 = sm4 + 4096;
    float4* X  = sm4 + 8192;
    int tid = threadIdx.x, tx = tid & 15, ty = tid >> 4;
    int base = blockIdx.x * ROWS;

    prefetch_rows(X, agts, base, N_AGT, tid); CP_COMMIT();
    prefetch_w(W0, g_wt + 5 * 16384, tid);    CP_COMMIT();
    prefetch_w(W1, g_wt + 3 * 16384, tid);    CP_COMMIT();

    float v[4][8];
    CP_WAIT(1);
    __syncthreads();

    gemm_tile(X, W0, tx, ty, v);
#pragma unroll
    for (int r = 0; r < 4; r++) {
        int row = base + ty * 4 + r;
        if (row < N_AGT)
#pragma unroll
            for (int c = 0; c < 8; c++)
                g_abase[(size_t)row * D + tx + 16 * c] = v[r][c];
    }
    __syncthreads();
    prefetch_w(W0, g_wt + 4 * 16384, tid); CP_COMMIT();
    CP_WAIT(1);
    __syncthreads();

    gemm_tile(X, W1, tx, ty, v);
    {
        float gg[8], bb[8];
        load_gb(gq, bq, tx, gg, bb);
        gn_rows(v, gg, bb, true);
    }
    __syncthreads();
    store_tile_f4((float*)X, v, tx, ty);
    CP_WAIT(0);
    __syncthreads();

    gemm_tile(X, W0, tx, ty, v);
#pragma unroll
    for (int r = 0; r < 4; r++) {
        int row = base + ty * 4 + r;
        if (row < N_AGT)
#pragma unroll
            for (int c = 0; c < 8; c++)
                g_qc[(size_t)row * D + tx + 16 * c] = v[r][c];
    }
}

// ---------------------------------------------------------------------------
// Ctx kernel (SIMT)
// ---------------------------------------------------------------------------
__global__ __launch_bounds__(TPB, 1)
void ctx_kernel(const float* __restrict__ ctx) {
    extern __shared__ float4 sm4[];
    float4* W0 = sm4;
    float4* X  = sm4 + 4096;
    int tid = threadIdx.x, tx = tid & 15, ty = tid >> 4;
    int base = blockIdx.x * ROWS;

    prefetch_rows(X, ctx, base, N_CTX, tid); CP_COMMIT();
    prefetch_w(W0, g_wt + 7 * 16384, tid);    CP_COMMIT();
    CP_WAIT(0);
    __syncthreads();

    float v[4][8];
    gemm_tile(X, W0, tx, ty, v);
#pragma unroll
    for (int r = 0; r < 4; r++) {
        int row = base + ty * 4 + r;
        if (row < N_CTX)
#pragma unroll
            for (int c = 0; c < 8; c++)
                g_cc[(size_t)row * D + tx + 16 * c] = v[r][c];
    }
}

// ===========================================================================
// Edge kernel via mma.sync tf32, split-N warp tiling.
// 256 threads = 8 warps; warp pair (wp = wid>>1) owns rows [32wp, 32wp+32);
// ch = wid&1 selects the col half [64ch, 64ch+64).
// B operands fragment-packed in smem (LDS.64, conflict-free, half traffic/warp).
// GroupNorm partials exchanged across the warp pair via sred/qred.
// ===========================================================================

// stage a packed 64KB B matrix (already fragment-ordered) into smem
__device__ __forceinline__ void stage_wp(float* dst, const float* __restrict__ src, int tid) {
    unsigned int sb = (unsigned int)__cvta_generic_to_shared(dst);
#pragma unroll
    for (int i = 0; i < 16; i++) {
        int c = tid + i * ETPB;          // 0..4095 float4 chunks
        cp_async16(sb + (unsigned int)(c * 16), src + c * 4);
    }
}

// warp GEMM: rows [wr, wr+32), cols [64ch, 64ch+64)
// c[nt] = rows (wr+qr, wr+8+qr); c[8+nt] = rows (wr+16+qr, wr+24+qr)
__device__ __forceinline__ void wgemm2(const float* __restrict__ Xs,
                                       const float* __restrict__ Bpk,
                                       int wr, int ch, int lane, float c[16][4]) {
    int qr = lane >> 2, ql = lane & 3;
#pragma unroll
    for (int i = 0; i < 16; i++)
#pragma unroll
        for (int j = 0; j < 4; j++) c[i][j] = 0.f;

    const float* x0 = Xs + (wr + qr) * XSTR;
    const float* x1 = Xs + (wr + 16 + qr) * XSTR;
    const float2* bp = (const float2*)Bpk + ch * 8 * 32 + lane;

#pragma unroll
    for (int ks = 0; ks < 16; ks++) {
        int k0 = ks * 8;
        unsigned a00 = __float_as_uint(x0[k0 + ql]);
        unsigned a01 = __float_as_uint(x0[8 * XSTR + k0 + ql]);
        unsigned a02 = __float_as_uint(x0[k0 + 4 + ql]);
        unsigned a03 = __float_as_uint(x0[8 * XSTR + k0 + 4 + ql]);
        unsigned a10 = __float_as_uint(x1[k0 + ql]);
        unsigned a11 = __float_as_uint(x1[8 * XSTR + k0 + ql]);
        unsigned a12 = __float_as_uint(x1[k0 + 4 + ql]);
        unsigned a13 = __float_as_uint(x1[8 * XSTR + k0 + 4 + ql]);
        const float2* bk = bp + ks * 16 * 32;
#pragma unroll
        for (int nt = 0; nt < 8; nt++) {
            float2 b = bk[nt * 32];
            unsigned b0 = __float_as_uint(b.x), b1 = __float_as_uint(b.y);
            mma8(c[nt],     a00, a01, a02, a03, b0, b1);
            mma8(c[8 + nt], a10, a11, a12, a13, b0, b1);
        }
    }
}

// GroupNorm(+relu) epilogue on split-N fragments; optional +qc[hi]+cc[wi];
// cross-pair reduction via sred/qred; writes tf32 result back into Xs.
// Contains one __syncthreads (all threads must call).
template <bool GATHER>
__device__ __forceinline__ void epi_gn2(float c[16][4], float* __restrict__ Xs,
                                        const float* __restrict__ gv,
                                        const float* __restrict__ bv,
                                        const int* s_hi, const int* s_wi,
                                        float* sred, float* qred,
                                        int wr, int ch, int lane) {
    int qr = lane >> 2, ql = lane & 3;
    int r0 = wr + qr, r1 = wr + 8 + qr, r2 = wr + 16 + qr, r3 = wr + 24 + qr;

    if (GATHER) {
        const float* qp0 = g_qc + (size_t)s_hi[r0] * D;
        const float* cp0 = g_cc + (size_t)s_wi[r0] * D;
        const float* qp1 = g_qc + (size_t)s_hi[r1] * D;
        const float* cp1 = g_cc + (size_t)s_wi[r1] * D;
        const float* qp2 = g_qc + (size_t)s_hi[r2] * D;
        const float* cp2 = g_cc + (size_t)s_wi[r2] * D;
        const float* qp3 = g_qc + (size_t)s_hi[r3] * D;
        const float* cp3 = g_cc + (size_t)s_wi[r3] * D;
#pragma unroll 4
        for (int nt = 0; nt < 8; nt++) {
            int col = ch * 64 + nt * 8 + 2 * ql;
            float2 a, b;
            a = *(const float2*)(qp0 + col); b = *(const float2*)(cp0 + col);
            c[nt][0] += a.x + b.x;      c[nt][1] += a.y + b.y;
            a = *(const float2*)(qp1 + col); b = *(const float2*)(cp1 + col);
            c[nt][2] += a.x + b.x;      c[nt][3] += a.y + b.y;
            a = *(const float2*)(qp2 + col); b = *(const float2*)(cp2 + col);
            c[8 + nt][0] += a.x + b.x;  c[8 + nt][1] += a.y + b.y;
            a = *(const float2*)(qp3 + col); b = *(const float2*)(cp3 + col);
            c[8 + nt][2] += a.x + b.x;  c[8 + nt][3] += a.y + b.y;
        }
    }

    float s[4] = {0.f, 0.f, 0.f, 0.f}, q[4] = {0.f, 0.f, 0.f, 0.f};
#pragma unroll
    for (int nt = 0; nt < 8; nt++) {
        s[0] += c[nt][0] + c[nt][1];
        q[0] += c[nt][0] * c[nt][0] + c[nt][1] * c[nt][1];
        s[1] += c[nt][2] + c[nt][3];
        q[1] += c[nt][2] * c[nt][2] + c[nt][3] * c[nt][3];
        s[2] += c[8 + nt][0] + c[8 + nt][1];
        q[2] += c[8 + nt][0] * c[8 + nt][0] + c[8 + nt][1] * c[8 + nt][1];
        s[3] += c[8 + nt][2] + c[8 + nt][3];
        q[3] += c[8 + nt][2] * c[8 + nt][2] + c[8 + nt][3] * c[8 + nt][3];
    }
#pragma unroll
    for (int off = 1; off < 4; off <<= 1) {
#pragma unroll
        for (int i = 0; i < 4; i++) {
            s[i] += __shfl_xor_sync(0xFFFFFFFFu, s[i], off);
            q[i] += __shfl_xor_sync(0xFFFFFFFFu, q[i], off);
        }
    }
    if (ql == 0) {
        sred[r0 * 2 + ch] = s[0]; qred[r0 * 2 + ch] = q[0];
        sred[r1 * 2 + ch] = s[1]; qred[r1 * 2 + ch] = q[1];
        sred[r2 * 2 + ch] = s[2]; qred[r2 * 2 + ch] = q[2];
        sred[r3 * 2 + ch] = s[3]; qred[r3 * 2 + ch] = q[3];
    }
    __syncthreads();

    float mu[4], rstd[4];
    int rr[4] = {r0, r1, r2, r3};
#pragma unroll
    for (int i = 0; i < 4; i++) {
        float ss = sred[rr[i] * 2] + sred[rr[i] * 2 + 1];
        float qq = qred[rr[i] * 2] + qred[rr[i] * 2 + 1];
        mu[i] = ss * (1.f / 128.f);
        rstd[i] = rsqrtf(fmaxf(qq * (1.f / 128.f) - mu[i] * mu[i], 0.f) + 1e-5f);
    }
#pragma unroll
    for (int nt = 0; nt < 8; nt++) {
        int col = ch * 64 + nt * 8 + 2 * ql;
        float2 g2 = *(const float2*)(gv + col);
        float2 b2 = *(const float2*)(bv + col);
        float2 y;
        y.x = tf32r(fmaxf((c[nt][0] - mu[0]) * rstd[0] * g2.x + b2.x, 0.f));
        y.y = tf32r(fmaxf((c[nt][1] - mu[0]) * rstd[0] * g2.y + b2.y, 0.f));
        *(float2*)(Xs + r0 * XSTR + col) = y;
        y.x = tf32r(fmaxf((c[nt][2] - mu[1]) * rstd[1] * g2.x + b2.x, 0.f));
        y.y = tf32r(fmaxf((c[nt][3] - mu[1]) * rstd[1] * g2.y + b2.y, 0.f));
        *(float2*)(Xs + r1 * XSTR + col) = y;
        y.x = tf32r(fmaxf((c[8 + nt][0] - mu[2]) * rstd[2] * g2.x + b2.x, 0.f));
        y.y = tf32r(fmaxf((c[8 + nt][1] - mu[2]) * rstd[2] * g2.y + b2.y, 0.f));
        *(float2*)(Xs + r2 * XSTR + col) = y;
        y.x = tf32r(fmaxf((c[8 + nt][2] - mu[3]) * rstd[3] * g2.x + b2.x, 0.f));
        y.y = tf32r(fmaxf((c[8 + nt][3] - mu[3]) * rstd[3] * g2.y + b2.y, 0.f));
        *(float2*)(Xs + r3 * XSTR + col) = y;
    }
    __syncwarp();
}

__global__ __launch_bounds__(ETPB, 1)
void edge_kernel_m(const float* __restrict__ agt_ctrs, const float* __restrict__ ctx_ctrs,
                   const float* __restrict__ W_dist1, const float* __restrict__ b_dist1,
                   const float* __restrict__ g_dist, const float* __restrict__ b_dist,
                   const float* __restrict__ g_c1, const float* __restrict__ b_c1,
                   const int* __restrict__ hi, const int* __restrict__ wi) {
    extern __shared__ float sm[];
    float* Xs = sm;                       // 128*132 = 16896 floats
    float* Wa = sm + 16896;               // 16384
    float* Wb = sm + 33280;               // 16384
    int* s_hi    = (int*)(sm + 49664);    // 128
    int* s_wi    = (int*)(sm + 49792);    // 128
    float* s_dxy = sm + 49920;            // 256
    float* sred  = sm + 50176;            // 256: [row][ch]
    float* qred  = sm + 50432;            // 256

    int tid = threadIdx.x, lane = tid & 31, wid = tid >> 5;
    int wr = (wid >> 1) * 32;             // warp-pair row base
    int ch = wid & 1;                     // col half
    int e0 = blockIdx.x * 128;

    stage_wp(Wa, g_wp + 0 * 16384, tid); CP_COMMIT();   // G0: dist2 (packed)
    stage_wp(Wb, g_wp + 1 * 16384, tid); CP_COMMIT();   // G1: c1top (packed)

    if (tid < 128) {
        int e = e0 + tid;
        if (e > NE - 1) e = NE - 1;
        int h = hi[e], w = wi[e];
        s_hi[tid] = h;
        s_wi[tid] = w;
        s_dxy[2 * tid]     = agt_ctrs[2 * h]     - ctx_ctrs[2 * w];
        s_dxy[2 * tid + 1] = agt_ctrs[2 * h + 1] - ctx_ctrs[2 * w + 1];
    }
    __syncthreads();

    // H1 = relu(dxy @ W_dist1 + b1) -> Xs (tf32); warp covers 16 rows x 128 cols
    {
        int row = wid * 16 + (lane >> 1);
        int kg0 = (lane & 1) * 16;
        float dx = s_dxy[2 * row], dy = s_dxy[2 * row + 1];
#pragma unroll 4
        for (int i = 0; i < 16; i++) {
            int kg = kg0 + i;
            float4 w0 = *(const float4*)(W_dist1 + kg * 4);
            float4 w1 = *(const float4*)(W_dist1 + 128 + kg * 4);
            float4 bb = *(const float4*)(b_dist1 + kg * 4);
            float4 h;
            h.x = tf32r(fmaxf(fmaf(dx, w0.x, fmaf(dy, w1.x, bb.x)), 0.f));
            h.y = tf32r(fmaxf(fmaf(dx, w0.y, fmaf(dy, w1.y, bb.y)), 0.f));
            h.z = tf32r(fmaxf(fmaf(dx, w0.z, fmaf(dy, w1.z, bb.z)), 0.f));
            h.w = tf32r(fmaxf(fmaf(dx, w0.w, fmaf(dy, w1.w, bb.w)), 0.f));
            *(float4*)(Xs + row * XSTR + kg * 4) = h;
        }
    }
    CP_WAIT(1);          // Wa (dist2) landed
    __syncthreads();

    float c[16][4];

    // GEMM1 + epi1: d = relu(gn(H1 @ W_dist2)) -> Xs
    wgemm2(Xs, Wa, wr, ch, lane, c);
    epi_gn2<false>(c, Xs, g_dist, b_dist, nullptr, nullptr, sred, qred, wr, ch, lane);
    __syncthreads();                                      // all done with Wa + Xs written
    stage_wp(Wa, g_wp + 2 * 16384, tid); CP_COMMIT();     // G2: c2 (packed)
    CP_WAIT(1);          // Wb (c1top) landed
    __syncthreads();

    // GEMM2 + epi2: c1 = relu(gn(d @ W_c1top + qc[hi] + cc[wi])) -> Xs
    wgemm2(Xs, Wb, wr, ch, lane, c);
    epi_gn2<true>(c, Xs, g_c1, b_c1, s_hi, s_wi, sred, qred, wr, ch, lane);
    CP_WAIT(0);          // Wa (c2) landed
    __syncthreads();

    // GEMM3: out = c1 @ W_c2 -> vector red scatter into g_abase[hi]
    wgemm2(Xs, Wa, wr, ch, lane, c);
    {
        int qr = lane >> 2, ql = lane & 3;
        int r0 = wr + qr, r1 = wr + 8 + qr, r2 = wr + 16 + qr, r3 = wr + 24 + qr;
        bool ok0 = (e0 + r0) < NE, ok1 = (e0 + r1) < NE;
        bool ok2 = (e0 + r2) < NE, ok3 = (e0 + r3) < NE;
        float* a0 = g_abase + (size_t)s_hi[r0] * D;
        float* a1 = g_abase + (size_t)s_hi[r1] * D;
        float* a2 = g_abase + (size_t)s_hi[r2] * D;
        float* a3 = g_abase + (size_t)s_hi[r3] * D;
#pragma unroll
        for (int nt = 0; nt < 8; nt++) {
            int col = ch * 64 + nt * 8 + 2 * ql;
            if (ok0)
                asm volatile("red.global.add.v2.f32 [%0], {%1,%2};"
                             :: "l"(a0 + col), "f"(c[nt][0]), "f"(c[nt][1]) : "memory");
            if (ok1)
                asm volatile("red.global.add.v2.f32 [%0], {%1,%2};"
                             :: "l"(a1 + col), "f"(c[nt][2]), "f"(c[nt][3]) : "memory");
            if (ok2)
                asm volatile("red.global.add.v2.f32 [%0], {%1,%2};"
                             :: "l"(a2 + col), "f"(c[8 + nt][0]), "f"(c[8 + nt][1]) : "memory");
            if (ok3)
                asm volatile("red.global.add.v2.f32 [%0], {%1,%2};"
                             :: "l"(a3 + col), "f"(c[8 + nt][2]), "f"(c[8 + nt][3]) : "memory");
        }
    }
}

// ---------------------------------------------------------------------------
// Final kernel (SIMT)
// ---------------------------------------------------------------------------
__global__ __launch_bounds__(TPB, 1)
void final_kernel(const float* __restrict__ agts,
                  const float* __restrict__ gn_g, const float* __restrict__ gn_b,
                  const float* __restrict__ gl_g, const float* __restrict__ gl_b,
                  float* __restrict__ out) {
    extern __shared__ float4 sm4[];
    float4* W0 = sm4;
    float4* X  = sm4 + 4096;
    int tid = threadIdx.x, tx = tid & 15, ty = tid >> 4;
    int base = blockIdx.x * ROWS;

    prefetch_rows(X, g_abase, base, N_AGT, tid); CP_COMMIT();
    prefetch_w(W0, g_wt + 6 * 16384, tid);        CP_COMMIT();
    CP_WAIT(0);
    __syncthreads();

    float v[4][8];
    float* Xf = (float*)X;
#pragma unroll
    for (int r = 0; r < 4; r++)
#pragma unroll
        for (int c = 0; c < 8; c++) {
            int col = tx + 16 * c, row = ty * 4 + r;
            v[r][c] = Xf[((col >> 2) * 128 + row) * 4 + (col & 3)];
        }
    {
        float gg[8], bb[8];
        load_gb(gn_g, gn_b, tx, gg, bb);
        gn_rows(v, gg, bb, true);
    }
    store_tile_f4(Xf, v, tx, ty);
    __syncthreads();

    gemm_tile(X, W0, tx, ty, v);
    {
        float gg[8], bb[8];
        load_gb(gl_g, gl_b, tx, gg, bb);
        gn_rows(v, gg, bb, false);
    }
#pragma unroll
    for (int r = 0; r < 4; r++) {
        int row = base + ty * 4 + r;
        if (row < N_AGT) {
#pragma unroll
            for (int c = 0; c < 8; c++) {
                int col = tx + 16 * c;
                float t = v[r][c] + agts[(size_t)row * D + col];
                out[(size_t)row * D + col] = fmaxf(t, 0.f);
            }
        }
    }
}

// ---------------------------------------------------------------------------
// Launch
// ---------------------------------------------------------------------------
extern "C" void kernel_launch(void* const* d_in, const int* in_sizes, int n_in,
                              void* d_out, int out_size) {
    const float* agts     = (const float*)d_in[0];
    const float* ctx      = (const float*)d_in[1];
    const float* agt_ctrs = (const float*)d_in[2];
    const float* ctx_ctrs = (const float*)d_in[3];
    const float* W_dist1  = (const float*)d_in[4];
    const float* b_dist1  = (const float*)d_in[5];
    const float* W_dist2  = (const float*)d_in[6];
    const float* g_dist   = (const float*)d_in[7];
    const float* b_dist   = (const float*)d_in[8];
    const float* W_q      = (const float*)d_in[9];
    const float* g_q      = (const float*)d_in[10];
    const float* b_q      = (const float*)d_in[11];
    const float* W_c1     = (const float*)d_in[12];
    const float* g_c1     = (const float*)d_in[13];
    const float* b_c1     = (const float*)d_in[14];
    const float* W_c2     = (const float*)d_in[15];
    const float* W_agt    = (const float*)d_in[16];
    const float* g_n      = (const float*)d_in[17];
    const float* b_n      = (const float*)d_in[18];
    const float* W_lin    = (const float*)d_in[19];
    const float* g_lin    = (const float*)d_in[20];
    const float* b_lin    = (const float*)d_in[21];
    const int*   hi       = (const int*)d_in[22];
    const int*   wi       = (const int*)d_in[23];
    float* outp = (float*)d_out;

    const int AGENT_SMEM = 12288 * 16;          // 196608
    const int SML_SMEM   = 8192 * 16;           // 131072
    const int EDGE_SMEM  = 50688 * 4;           // 202752

    cudaFuncSetAttribute(agent_kernel,  cudaFuncAttributeMaxDynamicSharedMemorySize, AGENT_SMEM);
    cudaFuncSetAttribute(ctx_kernel,    cudaFuncAttributeMaxDynamicSharedMemorySize, SML_SMEM);
    cudaFuncSetAttribute(edge_kernel_m, cudaFuncAttributeMaxDynamicSharedMemorySize, EDGE_SMEM);
    cudaFuncSetAttribute(final_kernel,  cudaFuncAttributeMaxDynamicSharedMemorySize, SML_SMEM);

    // 1) weight prep: SIMT transposes + fragment-packed tf32 B operands
    transpose_all<<<320, 256>>>(W_q, W_c1, W_agt, W_lin);
    pack_b<<<192, 256>>>(W_dist2, W_c1, W_c2);

    // 2) per-node precomputes (SIMT)
    agent_kernel<<<(N_AGT + ROWS - 1) / ROWS, TPB, AGENT_SMEM>>>(agts, g_q, b_q);
    ctx_kernel<<<(N_CTX + ROWS - 1) / ROWS, TPB, SML_SMEM>>>(ctx);

    // 3) per-edge pipeline on tensor cores (mma.sync tf32, split-N) + red scatter
    edge_kernel_m<<<(NE + 127) / 128, ETPB, EDGE_SMEM>>>(agt_ctrs, ctx_ctrs,
                                                         W_dist1, b_dist1,
                                                         g_dist, b_dist,
                                                         g_c1, b_c1,
                                                         hi, wi);

    // 4) final norm + linear + residual (SIMT)
    final_kernel<<<(N_AGT + ROWS - 1) / ROWS, TPB, SML_SMEM>>>(agts, g_n, b_n,
                                                               g_lin, b_lin, outp);
}